// round 15
// baseline (speedup 1.0000x reference)
#include <cuda_runtime.h>
#include <cuda_fp16.h>
#include <cstdint>
#include <math.h>

#define THREADS 128
#define NITER   32
#define BM      128
#define NSTAGE  6
#define SCALEQ  0.3535533905932738f    // 8^-0.5
#define SCALEK  0.5100697280f          // log2(e) * 8^-0.5  (exp -> bare ex2)

// smem layout (bytes)
#define SM_Q       0              // 64 c-rows x 256B (128 t fp16) = 16384
#define SM_BUF     16384          // 6 stages x (K 8192 + V 8192)
#define TILE_K     8192
#define BUF_STRIDE 16384
#define SMEM_BYTES 114688         // 16384 + 6*16384; epilogue [128][65]f32 (33280) fits

// fp16 pre-converted, pre-swizzled K/V scratch: [bh(32)][tile(32)][8192B]
__device__ __align__(16) unsigned char g_ks[32 * 32 * 8192];
__device__ __align__(16) unsigned char g_vs[32 * 32 * 8192];

__device__ __forceinline__ uint32_t smem_u32(const void* p) {
    uint32_t a;
    asm("{ .reg .u64 t; cvta.to.shared.u64 t, %1; cvt.u32.u64 %0, t; }" : "=r"(a) : "l"(p));
    return a;
}
__device__ __forceinline__ uint32_t h2pack(float lo, float hi) {
    uint32_t r;
    asm("cvt.rn.f16x2.f32 %0, %1, %2;" : "=r"(r) : "f"(hi), "f"(lo));
    return r;
}
__device__ __forceinline__ uint32_t ex2h2(uint32_t x) {
    uint32_t r;
    asm("ex2.approx.f16x2 %0, %1;" : "=r"(r) : "r"(x));
    return r;
}
__device__ __forceinline__ uint32_t hadd2(uint32_t a, uint32_t b) {
    uint32_t r;
    asm("add.rn.f16x2 %0, %1, %2;" : "=r"(r) : "r"(a), "r"(b));
    return r;
}
__device__ __forceinline__ void cp16(uint32_t dst, const void* src) {
    asm volatile("cp.async.cg.shared.global [%0], [%1], 16;" :: "r"(dst), "l"(src) : "memory");
}
#define CP_COMMIT() asm volatile("cp.async.commit_group;" ::: "memory")
__device__ __forceinline__ void ldsm4(uint32_t* r, uint32_t a) {
    asm volatile("ldmatrix.sync.aligned.m8n8.x4.shared.b16 {%0,%1,%2,%3}, [%4];"
                 : "=r"(r[0]), "=r"(r[1]), "=r"(r[2]), "=r"(r[3]) : "r"(a));
}
__device__ __forceinline__ void ldsm4t(uint32_t* r, uint32_t a) {
    asm volatile("ldmatrix.sync.aligned.m8n8.x4.trans.shared.b16 {%0,%1,%2,%3}, [%4];"
                 : "=r"(r[0]), "=r"(r[1]), "=r"(r[2]), "=r"(r[3]) : "r"(a));
}
__device__ __forceinline__ void mma16(float* d, const uint32_t* a, uint32_t b0, uint32_t b1) {
    asm volatile("mma.sync.aligned.m16n8k16.row.col.f32.f16.f16.f32 "
                 "{%0,%1,%2,%3}, {%4,%5,%6,%7}, {%8,%9}, {%0,%1,%2,%3};"
                 : "+f"(d[0]), "+f"(d[1]), "+f"(d[2]), "+f"(d[3])
                 : "r"(a[0]), "r"(a[1]), "r"(a[2]), "r"(a[3]), "r"(b0), "r"(b1));
}
__device__ __forceinline__ uint4 pack8(float4 x, float4 y, float s) {
    uint4 u;
    u.x = h2pack(x.x * s, x.y * s);
    u.y = h2pack(x.z * s, x.w * s);
    u.z = h2pack(y.x * s, y.y * s);
    u.w = h2pack(y.z * s, y.w * s);
    return u;
}

// ---- pre-pass: convert K/V to fp16 in swizzled tile layout, scale folded ----
__global__ void __launch_bounds__(256)
conv_kv(const float* __restrict__ qkv) {
    const int tile = blockIdx.x, bh = blockIdx.y;
    const int b = bh >> 3, h = bh & 7;
    const float* basep = qkv + ((long)b * 1536 + h * 192) * 2048;
    const int tid = threadIdx.x;
    const int cst = tid >> 2, s16 = (tid & 3) << 4;
    const uint32_t xrs = (uint32_t)(cst & 7) << 4;
    const uint32_t bcol = (uint32_t)s16 << 1;
    const float* ks = basep + 64L * 2048 + tile * 64 + (long)cst * 2048 + s16;
    const float* vs = basep + 128L * 2048 + tile * 64 + (long)cst * 2048 + s16;
    float4 k0 = *(const float4*)(ks),     k1 = *(const float4*)(ks + 4);
    float4 k2 = *(const float4*)(ks + 8), k3 = *(const float4*)(ks + 12);
    float4 v0 = *(const float4*)(vs),     v1 = *(const float4*)(vs + 4);
    float4 v2 = *(const float4*)(vs + 8), v3 = *(const float4*)(vs + 12);
    unsigned char* kd = g_ks + (((uint32_t)bh * 32 + tile) << 13) + (cst << 7);
    unsigned char* vd = g_vs + (((uint32_t)bh * 32 + tile) << 13) + (cst << 7);
    *(uint4*)(kd + ((bcol)      ^ xrs)) = pack8(k0, k1, SCALEK);
    *(uint4*)(kd + ((bcol + 16) ^ xrs)) = pack8(k2, k3, SCALEK);
    *(uint4*)(vd + ((bcol)      ^ xrs)) = pack8(v0, v1, 1.f);
    *(uint4*)(vd + ((bcol + 16) ^ xrs)) = pack8(v2, v3, 1.f);
}

__global__ void __launch_bounds__(THREADS, 2)
attn_r15(const float* __restrict__ qkv, float* __restrict__ out) {
    extern __shared__ char smem[];
    const uint32_t S = smem_u32(smem);
    const int tid = threadIdx.x, lane = tid & 31, warp = tid >> 5;
    const int j = lane & 7, grp = lane >> 3, g = lane >> 2, tg = lane & 3;
    const int m0 = warp * 32;
    const int qblk = blockIdx.x, bh = blockIdx.y;
    const int b = bh >> 3, h = bh & 7;
    const float* qp = qkv + ((long)b * 1536 + h * 192) * 2048;
    const unsigned char* ksrc = g_ks + ((uint32_t)bh << 18) + tid * 64;
    const unsigned char* vsrc = g_vs + ((uint32_t)bh << 18) + tid * 64;

    // ---- prologue: issue cp.async for tiles 0..3 into stages 0..3 ----
#pragma unroll
    for (int t0 = 0; t0 < 4; t0++) {
        uint32_t kd = S + SM_BUF + t0 * BUF_STRIDE + tid * 64;
        cp16(kd,      ksrc + (t0 << 13));
        cp16(kd + 16, ksrc + (t0 << 13) + 16);
        cp16(kd + 32, ksrc + (t0 << 13) + 32);
        cp16(kd + 48, ksrc + (t0 << 13) + 48);
        cp16(kd + TILE_K,      vsrc + (t0 << 13));
        cp16(kd + TILE_K + 16, vsrc + (t0 << 13) + 16);
        cp16(kd + TILE_K + 32, vsrc + (t0 << 13) + 32);
        cp16(kd + TILE_K + 48, vsrc + (t0 << 13) + 48);
        CP_COMMIT();
    }

    // ---- stage Q tile as fp16 [c][t] (256B rows, XOR-swizzled), scaled ----
#pragma unroll
    for (int rep = 0; rep < 4; rep++) {
        int idx = tid + rep * THREADS;
        int c = idx >> 3, t16 = (idx & 7) << 4;
        const float* src = qp + (long)c * 2048 + qblk * BM + t16;
        float4 f0 = *(const float4*)(src);
        float4 f1 = *(const float4*)(src + 4);
        float4 f2 = *(const float4*)(src + 8);
        float4 f3 = *(const float4*)(src + 12);
        uint32_t xr = (uint32_t)(c & 7) << 4;
        *(uint4*)(smem + SM_Q + (c << 8) + (((t16 << 1))      ^ xr)) = pack8(f0, f1, SCALEQ);
        *(uint4*)(smem + SM_Q + (c << 8) + (((t16 << 1) + 16) ^ xr)) = pack8(f2, f3, SCALEQ);
    }
    asm volatile("cp.async.wait_group 0;" ::: "memory");
    __syncthreads();

    // ---- Q fragments -> registers (A-frags via ldmatrix.trans on [c][t]) ----
    uint32_t qf[4][8];
    {
        uint32_t rbase = ((uint32_t)(grp >> 1) << 11) + ((uint32_t)j << 8);
        uint32_t c_lo = (((uint32_t)((m0 << 1) + ((grp & 1) << 4))) ^ ((uint32_t)j << 4));
        uint32_t c_hi = (((uint32_t)(((m0 + 16) << 1) + ((grp & 1) << 4))) ^ ((uint32_t)j << 4));
#pragma unroll
        for (int kk = 0; kk < 4; kk++) {
            ldsm4t(&qf[kk][0], S + SM_Q + (kk << 12) + rbase + c_lo);
            ldsm4t(&qf[kk][4], S + SM_Q + (kk << 12) + rbase + c_hi);
        }
    }

    // per-lane constant ldmatrix offsets for K ([c][s] 128B rows) and V
    const uint32_t rowk = (uint32_t)(((grp & 1) << 3) + j) << 7;
    const uint32_t rowv = ((uint32_t)(grp >> 1) << 10) + ((uint32_t)j << 7);
    uint32_t sbk[4], sbv[4];
#pragma unroll
    for (int p = 0; p < 4; p++) {
        sbk[p] = (uint32_t)((p << 5) + ((grp >> 1) << 4)) ^ ((uint32_t)j << 4);
        sbv[p] = (uint32_t)((p << 5) + ((grp & 1) << 4)) ^ ((uint32_t)j << 4);
    }

    float oa[16][4];
#pragma unroll
    for (int n = 0; n < 16; n++)
#pragma unroll
        for (int q = 0; q < 4; q++) oa[n][q] = 0.f;
    float ls0 = 0.f, ls1 = 0.f, ls2 = 0.f, ls3 = 0.f;

    int rst = 0, wst = 4;   // read / write stage indices (mod 6)
#pragma unroll 2
    for (int it = 0; it < NITER; ++it) {
        const uint32_t kb = S + SM_BUF + (uint32_t)rst * BUF_STRIDE;
        const uint32_t vb = kb + TILE_K;

        // issue cp.async for tile it+4 into stage wst
        if (it + 4 < NITER) {
            int tn = it + 4;
            uint32_t kd = S + SM_BUF + (uint32_t)wst * BUF_STRIDE + tid * 64;
            cp16(kd,      ksrc + (tn << 13));
            cp16(kd + 16, ksrc + (tn << 13) + 16);
            cp16(kd + 32, ksrc + (tn << 13) + 32);
            cp16(kd + 48, ksrc + (tn << 13) + 48);
            cp16(kd + TILE_K,      vsrc + (tn << 13));
            cp16(kd + TILE_K + 16, vsrc + (tn << 13) + 16);
            cp16(kd + TILE_K + 32, vsrc + (tn << 13) + 32);
            cp16(kd + TILE_K + 48, vsrc + (tn << 13) + 48);
            CP_COMMIT();
        }

        // ---- S = Q K^T  (M=32 per warp), log2-domain scores ----
        float sa[16][4];
#pragma unroll
        for (int n = 0; n < 16; n++)
#pragma unroll
            for (int q = 0; q < 4; q++) sa[n][q] = 0.f;
#pragma unroll
        for (int kk = 0; kk < 4; kk++) {
            uint32_t basek = kb + (kk << 11) + rowk;
#pragma unroll
            for (int np = 0; np < 4; np++) {
                uint32_t r[4];
                ldsm4t(r, basek + sbk[np]);
                mma16(sa[2 * np],         &qf[kk][0], r[0], r[1]);
                mma16(sa[2 * np + 1],     &qf[kk][0], r[2], r[3]);
                mma16(sa[8 + 2 * np],     &qf[kk][4], r[0], r[1]);
                mma16(sa[8 + 2 * np + 1], &qf[kk][4], r[2], r[3]);
            }
        }

        // ---- P = 2^S via f16x2 ex2; row sums via HADD2 (fma pipe); O += P V ----
        uint32_t hs0 = 0, hs1 = 0, hs2 = 0, hs3 = 0;
#pragma unroll
        for (int kk = 0; kk < 4; kk++) {
            uint32_t al[4], ah[4];
            al[0] = ex2h2(h2pack(sa[2 * kk][0],     sa[2 * kk][1]));
            al[1] = ex2h2(h2pack(sa[2 * kk][2],     sa[2 * kk][3]));
            al[2] = ex2h2(h2pack(sa[2 * kk + 1][0], sa[2 * kk + 1][1]));
            al[3] = ex2h2(h2pack(sa[2 * kk + 1][2], sa[2 * kk + 1][3]));
            ah[0] = ex2h2(h2pack(sa[8 + 2 * kk][0],     sa[8 + 2 * kk][1]));
            ah[1] = ex2h2(h2pack(sa[8 + 2 * kk][2],     sa[8 + 2 * kk][3]));
            ah[2] = ex2h2(h2pack(sa[8 + 2 * kk + 1][0], sa[8 + 2 * kk + 1][1]));
            ah[3] = ex2h2(h2pack(sa[8 + 2 * kk + 1][2], sa[8 + 2 * kk + 1][3]));
            hs0 = hadd2(hs0, hadd2(al[0], al[2]));
            hs1 = hadd2(hs1, hadd2(al[1], al[3]));
            hs2 = hadd2(hs2, hadd2(ah[0], ah[2]));
            hs3 = hadd2(hs3, hadd2(ah[1], ah[3]));
            uint32_t basev = vb + rowv + sbv[kk];
#pragma unroll
            for (int np = 0; np < 4; np++) {
                uint32_t r[4];
                ldsm4(r, basev + (np << 11));
                mma16(oa[2 * np],         al, r[0], r[1]);
                mma16(oa[2 * np + 1],     al, r[2], r[3]);
                mma16(oa[8 + 2 * np],     ah, r[0], r[1]);
                mma16(oa[8 + 2 * np + 1], ah, r[2], r[3]);
            }
        }
        {
            float2 f0 = __half22float2(*reinterpret_cast<__half2*>(&hs0));
            float2 f1 = __half22float2(*reinterpret_cast<__half2*>(&hs1));
            float2 f2 = __half22float2(*reinterpret_cast<__half2*>(&hs2));
            float2 f3 = __half22float2(*reinterpret_cast<__half2*>(&hs3));
            ls0 += f0.x + f0.y;
            ls1 += f1.x + f1.y;
            ls2 += f2.x + f2.y;
            ls3 += f3.x + f3.y;
        }
        if (it & 1) {
            if (it + 4 < NITER)
                asm volatile("cp.async.wait_group 2;" ::: "memory");
            else
                asm volatile("cp.async.wait_group 0;" ::: "memory");
            __syncthreads();   // one barrier per 2 tiles (6-stage ring)
        }
        rst = (rst + 1 == NSTAGE) ? 0 : rst + 1;
        wst = (wst + 1 == NSTAGE) ? 0 : wst + 1;
    }

    // ---- epilogue: quad-reduce row sums, normalize, transpose via smem ----
    ls0 += __shfl_xor_sync(0xffffffffu, ls0, 1);
    ls0 += __shfl_xor_sync(0xffffffffu, ls0, 2);
    ls1 += __shfl_xor_sync(0xffffffffu, ls1, 1);
    ls1 += __shfl_xor_sync(0xffffffffu, ls1, 2);
    ls2 += __shfl_xor_sync(0xffffffffu, ls2, 1);
    ls2 += __shfl_xor_sync(0xffffffffu, ls2, 2);
    ls3 += __shfl_xor_sync(0xffffffffu, ls3, 1);
    ls3 += __shfl_xor_sync(0xffffffffu, ls3, 2);
    const float inv0 = 1.f / ls0, inv1 = 1.f / ls1;
    const float inv2 = 1.f / ls2, inv3 = 1.f / ls3;

    __syncthreads();
    float* ep = (float*)smem;   // [128][65]
#pragma unroll
    for (int n = 0; n < 8; n++) {
        ep[(m0 + g) * 65      + 8 * n + 2 * tg]     = oa[n][0] * inv0;
        ep[(m0 + g) * 65      + 8 * n + 2 * tg + 1] = oa[n][1] * inv0;
        ep[(m0 + 8 + g) * 65  + 8 * n + 2 * tg]     = oa[n][2] * inv1;
        ep[(m0 + 8 + g) * 65  + 8 * n + 2 * tg + 1] = oa[n][3] * inv1;
        ep[(m0 + 16 + g) * 65 + 8 * n + 2 * tg]     = oa[8 + n][0] * inv2;
        ep[(m0 + 16 + g) * 65 + 8 * n + 2 * tg + 1] = oa[8 + n][1] * inv2;
        ep[(m0 + 24 + g) * 65 + 8 * n + 2 * tg]     = oa[8 + n][2] * inv3;
        ep[(m0 + 24 + g) * 65 + 8 * n + 2 * tg + 1] = oa[8 + n][3] * inv3;
    }
    __syncthreads();

    float* outp = out + ((long)b * 512 + h * 64) * 2048 + qblk * BM;
    for (int i = tid; i < 64 * BM; i += THREADS) {
        int cc = i >> 7, t = i & (BM - 1);
        outp[(long)cc * 2048 + t] = ep[t * 65 + cc];
    }
}

extern "C" void kernel_launch(void* const* d_in, const int* in_sizes, int n_in,
                              void* d_out, int out_size) {
    const float* qkv = (const float*)d_in[0];
    float* out = (float*)d_out;
    cudaFuncSetAttribute(attn_r15, cudaFuncAttributeMaxDynamicSharedMemorySize, SMEM_BYTES);
    dim3 cgrid(32, 32);
    conv_kv<<<cgrid, 256>>>(qkv);
    dim3 grid(2048 / BM, 32);   // (16, 32) = 512 CTAs, 2 CTAs/SM
    attn_r15<<<grid, THREADS, SMEM_BYTES>>>(qkv, out);
}

// round 16
// speedup vs baseline: 1.1167x; 1.1167x over previous
#include <cuda_runtime.h>
#include <cuda_fp16.h>
#include <cstdint>
#include <math.h>

#define THREADS 256
#define NITER   32
#define BM      256
#define SCALEQ  0.3535533905932738f    // 8^-0.5
#define SCALEK  0.5100697280f          // log2(e) * 8^-0.5  (exp -> bare ex2)

// smem layout (bytes)
#define SM_Q       0              // 64 c-rows x 512B (256 t fp16) = 32768
#define SM_BUF     32768          // 8 stages x (K 8192 + V 8192)
#define TILE_K     8192
#define BUF_STRIDE 16384
#define SMEM_BYTES 163840         // 32768 + 8*16384; epilogue (66560) fits

// fp16 pre-converted, pre-swizzled K/V scratch: [bh(32)][tile(32)][8192B]
__device__ __align__(16) unsigned char g_ks[32 * 32 * 8192];
__device__ __align__(16) unsigned char g_vs[32 * 32 * 8192];

__device__ __forceinline__ uint32_t smem_u32(const void* p) {
    uint32_t a;
    asm("{ .reg .u64 t; cvta.to.shared.u64 t, %1; cvt.u32.u64 %0, t; }" : "=r"(a) : "l"(p));
    return a;
}
__device__ __forceinline__ uint32_t h2pack(float lo, float hi) {
    uint32_t r;
    asm("cvt.rn.f16x2.f32 %0, %1, %2;" : "=r"(r) : "f"(hi), "f"(lo));
    return r;
}
__device__ __forceinline__ uint32_t ex2h2(uint32_t x) {
    uint32_t r;
    asm("ex2.approx.f16x2 %0, %1;" : "=r"(r) : "r"(x));
    return r;
}
__device__ __forceinline__ uint32_t hadd2(uint32_t a, uint32_t b) {
    uint32_t r;
    asm("add.rn.f16x2 %0, %1, %2;" : "=r"(r) : "r"(a), "r"(b));
    return r;
}
__device__ __forceinline__ void cp16(uint32_t dst, const void* src) {
    asm volatile("cp.async.cg.shared.global [%0], [%1], 16;" :: "r"(dst), "l"(src) : "memory");
}
#define CP_COMMIT() asm volatile("cp.async.commit_group;" ::: "memory")
__device__ __forceinline__ void ldsm4(uint32_t* r, uint32_t a) {
    asm volatile("ldmatrix.sync.aligned.m8n8.x4.shared.b16 {%0,%1,%2,%3}, [%4];"
                 : "=r"(r[0]), "=r"(r[1]), "=r"(r[2]), "=r"(r[3]) : "r"(a));
}
__device__ __forceinline__ void ldsm4t(uint32_t* r, uint32_t a) {
    asm volatile("ldmatrix.sync.aligned.m8n8.x4.trans.shared.b16 {%0,%1,%2,%3}, [%4];"
                 : "=r"(r[0]), "=r"(r[1]), "=r"(r[2]), "=r"(r[3]) : "r"(a));
}
__device__ __forceinline__ void mma16(float* d, const uint32_t* a, uint32_t b0, uint32_t b1) {
    asm volatile("mma.sync.aligned.m16n8k16.row.col.f32.f16.f16.f32 "
                 "{%0,%1,%2,%3}, {%4,%5,%6,%7}, {%8,%9}, {%0,%1,%2,%3};"
                 : "+f"(d[0]), "+f"(d[1]), "+f"(d[2]), "+f"(d[3])
                 : "r"(a[0]), "r"(a[1]), "r"(a[2]), "r"(a[3]), "r"(b0), "r"(b1));
}
__device__ __forceinline__ uint4 pack8(float4 x, float4 y, float s) {
    uint4 u;
    u.x = h2pack(x.x * s, x.y * s);
    u.y = h2pack(x.z * s, x.w * s);
    u.z = h2pack(y.x * s, y.y * s);
    u.w = h2pack(y.z * s, y.w * s);
    return u;
}

// ---- pre-pass: convert K/V to fp16 in swizzled tile layout, scale folded ----
__global__ void __launch_bounds__(THREADS)
conv_kv(const float* __restrict__ qkv) {
    const int tile = blockIdx.x, bh = blockIdx.y;
    const int b = bh >> 3, h = bh & 7;
    const float* basep = qkv + ((long)b * 1536 + h * 192) * 2048;
    const int tid = threadIdx.x;
    const int cst = tid >> 2, s16 = (tid & 3) << 4;
    const uint32_t xrs = (uint32_t)(cst & 7) << 4;
    const uint32_t bcol = (uint32_t)s16 << 1;
    const float* ks = basep + 64L * 2048 + tile * 64 + (long)cst * 2048 + s16;
    const float* vs = basep + 128L * 2048 + tile * 64 + (long)cst * 2048 + s16;
    float4 k0 = *(const float4*)(ks),     k1 = *(const float4*)(ks + 4);
    float4 k2 = *(const float4*)(ks + 8), k3 = *(const float4*)(ks + 12);
    float4 v0 = *(const float4*)(vs),     v1 = *(const float4*)(vs + 4);
    float4 v2 = *(const float4*)(vs + 8), v3 = *(const float4*)(vs + 12);
    unsigned char* kd = g_ks + (((uint32_t)bh * 32 + tile) << 13) + (cst << 7);
    unsigned char* vd = g_vs + (((uint32_t)bh * 32 + tile) << 13) + (cst << 7);
    *(uint4*)(kd + ((bcol)      ^ xrs)) = pack8(k0, k1, SCALEK);
    *(uint4*)(kd + ((bcol + 16) ^ xrs)) = pack8(k2, k3, SCALEK);
    *(uint4*)(vd + ((bcol)      ^ xrs)) = pack8(v0, v1, 1.f);
    *(uint4*)(vd + ((bcol + 16) ^ xrs)) = pack8(v2, v3, 1.f);
    cudaTriggerProgrammaticLaunchCompletion();
}

__global__ void __launch_bounds__(THREADS, 1)
attn_r16(const float* __restrict__ qkv, float* __restrict__ out) {
    extern __shared__ char smem[];
    const uint32_t S = smem_u32(smem);
    const int tid = threadIdx.x, lane = tid & 31, warp = tid >> 5;
    const int j = lane & 7, grp = lane >> 3, g = lane >> 2, tg = lane & 3;
    const int m0 = warp * 32;
    const int qblk = blockIdx.x, bh = blockIdx.y;
    const int b = bh >> 3, h = bh & 7;
    const float* qp = qkv + ((long)b * 1536 + h * 192) * 2048;
    const unsigned char* ksrc = g_ks + ((uint32_t)bh << 18) + tid * 32;
    const unsigned char* vsrc = g_vs + ((uint32_t)bh << 18) + tid * 32;

    // ---- stage Q tile first (reads qkv only — overlaps pre-pass tail) ----
#pragma unroll
    for (int rep = 0; rep < 4; rep++) {
        int idx = tid + rep * THREADS;
        int c = idx >> 4, t16 = (idx & 15) << 4;
        const float* src = qp + (long)c * 2048 + qblk * BM + t16;
        float4 f0 = *(const float4*)(src);
        float4 f1 = *(const float4*)(src + 4);
        float4 f2 = *(const float4*)(src + 8);
        float4 f3 = *(const float4*)(src + 12);
        uint32_t xr = (uint32_t)(c & 7) << 4;
        *(uint4*)(smem + SM_Q + (c << 9) + (((t16 << 1))      ^ xr)) = pack8(f0, f1, SCALEQ);
        *(uint4*)(smem + SM_Q + (c << 9) + (((t16 << 1) + 16) ^ xr)) = pack8(f2, f3, SCALEQ);
    }

    // ---- wait for pre-pass stores to be visible, then start scratch reads ----
    cudaGridDependencySynchronize();

    // ---- prologue: issue cp.async for tiles 0..3 (one group per tile) ----
#pragma unroll
    for (int t0 = 0; t0 < 4; t0++) {
        uint32_t kd = S + SM_BUF + t0 * BUF_STRIDE + tid * 32;
        cp16(kd,            ksrc + (t0 << 13));
        cp16(kd + 16,       ksrc + (t0 << 13) + 16);
        cp16(kd + TILE_K,      vsrc + (t0 << 13));
        cp16(kd + TILE_K + 16, vsrc + (t0 << 13) + 16);
        CP_COMMIT();
    }
    asm volatile("cp.async.wait_group 0;" ::: "memory");
    __syncthreads();

    // ---- Q fragments -> registers (A-frags via ldmatrix.trans on [c][t]) ----
    uint32_t qf[4][8];
    {
        uint32_t rbase = ((uint32_t)(grp >> 1) << 12) + ((uint32_t)j << 9);
        uint32_t c_lo = (((uint32_t)((m0 << 1) + ((grp & 1) << 4))) ^ ((uint32_t)j << 4));
        uint32_t c_hi = (((uint32_t)(((m0 + 16) << 1) + ((grp & 1) << 4))) ^ ((uint32_t)j << 4));
#pragma unroll
        for (int kk = 0; kk < 4; kk++) {
            ldsm4t(&qf[kk][0], S + SM_Q + (kk << 13) + rbase + c_lo);
            ldsm4t(&qf[kk][4], S + SM_Q + (kk << 13) + rbase + c_hi);
        }
    }

    const uint32_t rowk = (uint32_t)(((grp & 1) << 3) + j) << 7;
    const uint32_t rowv = ((uint32_t)(grp >> 1) << 10) + ((uint32_t)j << 7);
    uint32_t sbk[4], sbv[4];
#pragma unroll
    for (int p = 0; p < 4; p++) {
        sbk[p] = (uint32_t)((p << 5) + ((grp >> 1) << 4)) ^ ((uint32_t)j << 4);
        sbv[p] = (uint32_t)((p << 5) + ((grp & 1) << 4)) ^ ((uint32_t)j << 4);
    }

    float oa[16][4];
#pragma unroll
    for (int n = 0; n < 16; n++)
#pragma unroll
        for (int q = 0; q < 4; q++) oa[n][q] = 0.f;
    float ls0 = 0.f, ls1 = 0.f, ls2 = 0.f, ls3 = 0.f;

#pragma unroll 2
    for (int it = 0; it < NITER; ++it) {
        const uint32_t kb = S + SM_BUF + ((uint32_t)(it & 7) * BUF_STRIDE);
        const uint32_t vb = kb + TILE_K;

        if (it + 4 < NITER) {
            int tn = it + 4;
            uint32_t kd = S + SM_BUF + ((uint32_t)(tn & 7) * BUF_STRIDE) + tid * 32;
            cp16(kd,            ksrc + (tn << 13));
            cp16(kd + 16,       ksrc + (tn << 13) + 16);
            cp16(kd + TILE_K,      vsrc + (tn << 13));
            cp16(kd + TILE_K + 16, vsrc + (tn << 13) + 16);
            CP_COMMIT();
        }

        // ---- S = Q K^T  (M=32 per warp), log2-domain scores ----
        float sa[16][4];
#pragma unroll
        for (int n = 0; n < 16; n++)
#pragma unroll
            for (int q = 0; q < 4; q++) sa[n][q] = 0.f;
#pragma unroll
        for (int kk = 0; kk < 4; kk++) {
            uint32_t basek = kb + (kk << 11) + rowk;
#pragma unroll
            for (int np = 0; np < 4; np++) {
                uint32_t r[4];
                ldsm4t(r, basek + sbk[np]);
                mma16(sa[2 * np],         &qf[kk][0], r[0], r[1]);
                mma16(sa[2 * np + 1],     &qf[kk][0], r[2], r[3]);
                mma16(sa[8 + 2 * np],     &qf[kk][4], r[0], r[1]);
                mma16(sa[8 + 2 * np + 1], &qf[kk][4], r[2], r[3]);
            }
        }

        // ---- P = 2^S via f16x2 ex2; row sums via HADD2 (fma pipe); O += P V ----
        uint32_t hs0 = 0, hs1 = 0, hs2 = 0, hs3 = 0;
#pragma unroll
        for (int kk = 0; kk < 4; kk++) {
            uint32_t al[4], ah[4];
            al[0] = ex2h2(h2pack(sa[2 * kk][0],     sa[2 * kk][1]));
            al[1] = ex2h2(h2pack(sa[2 * kk][2],     sa[2 * kk][3]));
            al[2] = ex2h2(h2pack(sa[2 * kk + 1][0], sa[2 * kk + 1][1]));
            al[3] = ex2h2(h2pack(sa[2 * kk + 1][2], sa[2 * kk + 1][3]));
            ah[0] = ex2h2(h2pack(sa[8 + 2 * kk][0],     sa[8 + 2 * kk][1]));
            ah[1] = ex2h2(h2pack(sa[8 + 2 * kk][2],     sa[8 + 2 * kk][3]));
            ah[2] = ex2h2(h2pack(sa[8 + 2 * kk + 1][0], sa[8 + 2 * kk + 1][1]));
            ah[3] = ex2h2(h2pack(sa[8 + 2 * kk + 1][2], sa[8 + 2 * kk + 1][3]));
            hs0 = hadd2(hs0, hadd2(al[0], al[2]));
            hs1 = hadd2(hs1, hadd2(al[1], al[3]));
            hs2 = hadd2(hs2, hadd2(ah[0], ah[2]));
            hs3 = hadd2(hs3, hadd2(ah[1], ah[3]));
            uint32_t basev = vb + rowv + sbv[kk];
#pragma unroll
            for (int np = 0; np < 4; np++) {
                uint32_t r[4];
                ldsm4(r, basev + (np << 11));
                mma16(oa[2 * np],         al, r[0], r[1]);
                mma16(oa[2 * np + 1],     al, r[2], r[3]);
                mma16(oa[8 + 2 * np],     ah, r[0], r[1]);
                mma16(oa[8 + 2 * np + 1], ah, r[2], r[3]);
            }
        }
        {
            float2 f0 = __half22float2(*reinterpret_cast<__half2*>(&hs0));
            float2 f1 = __half22float2(*reinterpret_cast<__half2*>(&hs1));
            float2 f2 = __half22float2(*reinterpret_cast<__half2*>(&hs2));
            float2 f3 = __half22float2(*reinterpret_cast<__half2*>(&hs3));
            ls0 += f0.x + f0.y;
            ls1 += f1.x + f1.y;
            ls2 += f2.x + f2.y;
            ls3 += f3.x + f3.y;
        }
        if (it & 1) {
            if (it + 4 < NITER)
                asm volatile("cp.async.wait_group 2;" ::: "memory");
            else
                asm volatile("cp.async.wait_group 0;" ::: "memory");
            __syncthreads();
        }
    }

    // ---- epilogue: quad-reduce row sums, normalize, transpose via smem ----
    ls0 += __shfl_xor_sync(0xffffffffu, ls0, 1);
    ls0 += __shfl_xor_sync(0xffffffffu, ls0, 2);
    ls1 += __shfl_xor_sync(0xffffffffu, ls1, 1);
    ls1 += __shfl_xor_sync(0xffffffffu, ls1, 2);
    ls2 += __shfl_xor_sync(0xffffffffu, ls2, 1);
    ls2 += __shfl_xor_sync(0xffffffffu, ls2, 2);
    ls3 += __shfl_xor_sync(0xffffffffu, ls3, 1);
    ls3 += __shfl_xor_sync(0xffffffffu, ls3, 2);
    const float inv0 = 1.f / ls0, inv1 = 1.f / ls1;
    const float inv2 = 1.f / ls2, inv3 = 1.f / ls3;

    __syncthreads();
    float* ep = (float*)smem;   // [256][65]
#pragma unroll
    for (int n = 0; n < 8; n++) {
        ep[(m0 + g) * 65      + 8 * n + 2 * tg]     = oa[n][0] * inv0;
        ep[(m0 + g) * 65      + 8 * n + 2 * tg + 1] = oa[n][1] * inv0;
        ep[(m0 + 8 + g) * 65  + 8 * n + 2 * tg]     = oa[n][2] * inv1;
        ep[(m0 + 8 + g) * 65  + 8 * n + 2 * tg + 1] = oa[n][3] * inv1;
        ep[(m0 + 16 + g) * 65 + 8 * n + 2 * tg]     = oa[8 + n][0] * inv2;
        ep[(m0 + 16 + g) * 65 + 8 * n + 2 * tg + 1] = oa[8 + n][1] * inv2;
        ep[(m0 + 24 + g) * 65 + 8 * n + 2 * tg]     = oa[8 + n][2] * inv3;
        ep[(m0 + 24 + g) * 65 + 8 * n + 2 * tg + 1] = oa[8 + n][3] * inv3;
    }
    __syncthreads();

    float* outp = out + ((long)b * 512 + h * 64) * 2048 + qblk * BM;
    for (int i = tid; i < 64 * BM; i += THREADS) {
        int cc = i >> 8, t = i & (BM - 1);
        outp[(long)cc * 2048 + t] = ep[t * 65 + cc];
    }
}

extern "C" void kernel_launch(void* const* d_in, const int* in_sizes, int n_in,
                              void* d_out, int out_size) {
    const float* qkv = (const float*)d_in[0];
    float* out = (float*)d_out;
    cudaFuncSetAttribute(attn_r16, cudaFuncAttributeMaxDynamicSharedMemorySize, SMEM_BYTES);

    dim3 cgrid(32, 32);
    conv_kv<<<cgrid, THREADS>>>(qkv);

    cudaLaunchConfig_t cfg = {};
    cfg.gridDim = dim3(2048 / BM, 32);   // (8, 32)
    cfg.blockDim = dim3(THREADS);
    cfg.dynamicSmemBytes = SMEM_BYTES;
    cudaLaunchAttribute attrs[1];
    attrs[0].id = cudaLaunchAttributeProgrammaticStreamSerialization;
    attrs[0].val.programmaticStreamSerializationAllowed = 1;
    cfg.attrs = attrs;
    cfg.numAttrs = 1;
    cudaLaunchKernelEx(&cfg, attn_r16, qkv, out);
}